// round 3
// baseline (speedup 1.0000x reference)
#include <cuda_runtime.h>
#include <cstdint>

// Problem constants
#define BATCHX 8
#define NSEQ   1024
#define EMBD   1024
#define HEADS  16
#define DHEAD  64
#define KDIM   1024
#define MROWS  (BATCHX * NSEQ)   // 8192

// Scratch (device globals: allocation-free per harness rules)
__device__ float g_q[BATCHX * HEADS * NSEQ * DHEAD];
__device__ float g_k[BATCHX * HEADS * NSEQ * DHEAD];
__device__ float g_v[BATCHX * HEADS * NSEQ * DHEAD];
__device__ float g_att[MROWS * EMBD];

// ===========================================================================
// tf32 warp-MMA GEMM (mma.sync m16n8k8 — compute_103-safe, no tcgen05)
// C[m,n] = sum_k A[m,k]*B[n,k].  Block tile 128x128, BK=16, 256 thr, 8 warps
// (2 M-halves x 4 N-quarters), warp tile 64x32 (4x4 mma tiles).
// SMEM holds operands in FRAGMENT ORDER so frag loads are conflict-free.
// ===========================================================================

__device__ __forceinline__ uint32_t f2tf32(float x) {
    uint32_t y;
    asm("cvt.rna.tf32.f32 %0, %1;" : "=r"(y) : "f"(x));
    return y;
}

__device__ __forceinline__ void mma_tf32(float* c, const uint32_t* a, const uint32_t* b) {
    asm volatile(
        "mma.sync.aligned.m16n8k8.row.col.f32.tf32.tf32.f32 "
        "{%0,%1,%2,%3}, {%4,%5,%6,%7}, {%8,%9}, {%0,%1,%2,%3};"
        : "+f"(c[0]), "+f"(c[1]), "+f"(c[2]), "+f"(c[3])
        : "r"(a[0]), "r"(a[1]), "r"(a[2]), "r"(a[3]), "r"(b[0]), "r"(b[1]));
}

// As: 2048 u32 (8KB) frag-ordered: [((t*2+s)*32 + lane)*4 + r]
//   t = 16-row group (0..7), s = k8 step (0..1), r = a-frag reg
// Bs: 2048 u32 (8KB): [((u*2+s)*32 + lane)*2 + r], u = 8-col group (0..15)
__device__ __forceinline__ void tf32_mainloop(const float* __restrict__ A,
                                              const float* __restrict__ B,
                                              int m0, int n0,
                                              uint32_t* As, uint32_t* Bs,
                                              float acc[4][4][4]) {
    const int tid = threadIdx.x;
    const int lane = tid & 31;
    const int wid = tid >> 5;
    const int wm = wid >> 2, wn = wid & 3;

    // Loader mapping: thread covers float4 #(tid + 256*i), i=0,1 for A and B.
    const int lrow = tid >> 2;        // 0..63 (+64 for i=1)
    const int lkb = tid & 3;          // which float4 within 16-wide k
    int baseA[2], baseB[2];
#pragma unroll
    for (int i = 0; i < 2; i++) {
        const int row = lrow + 64 * i;
        const int t = row >> 4, mi = row & 15;
        const int s = lkb >> 1;
        const int rA = (mi >> 3) + 2 * (lkb & 1);
        baseA[i] = ((t * 2 + s) * 32 + (mi & 7) * 4) * 4 + rA;
        const int u = row >> 3, ni = row & 7;
        baseB[i] = ((u * 2 + s) * 32 + ni * 4) * 2 + (lkb & 1);
    }
    const float* aptr0 = A + (size_t)(m0 + lrow) * KDIM + lkb * 4;
    const float* aptr1 = aptr0 + (size_t)64 * KDIM;
    const float* bptr0 = B + (size_t)(n0 + lrow) * KDIM + lkb * 4;
    const float* bptr1 = bptr0 + (size_t)64 * KDIM;

#pragma unroll
    for (int i = 0; i < 4; i++)
#pragma unroll
        for (int j = 0; j < 4; j++)
#pragma unroll
            for (int r = 0; r < 4; r++) acc[i][j][r] = 0.f;

    float4 pa0 = *(const float4*)aptr0;
    float4 pa1 = *(const float4*)aptr1;
    float4 pb0 = *(const float4*)bptr0;
    float4 pb1 = *(const float4*)bptr1;

    const int NST = KDIM / 16;   // 64 stages
    for (int st = 0; st < NST; st++) {
        __syncthreads();
        As[baseA[0] + 0]  = f2tf32(pa0.x);
        As[baseA[0] + 4]  = f2tf32(pa0.y);
        As[baseA[0] + 8]  = f2tf32(pa0.z);
        As[baseA[0] + 12] = f2tf32(pa0.w);
        As[baseA[1] + 0]  = f2tf32(pa1.x);
        As[baseA[1] + 4]  = f2tf32(pa1.y);
        As[baseA[1] + 8]  = f2tf32(pa1.z);
        As[baseA[1] + 12] = f2tf32(pa1.w);
        Bs[baseB[0] + 0]  = f2tf32(pb0.x);
        Bs[baseB[0] + 2]  = f2tf32(pb0.y);
        Bs[baseB[0] + 4]  = f2tf32(pb0.z);
        Bs[baseB[0] + 6]  = f2tf32(pb0.w);
        Bs[baseB[1] + 0]  = f2tf32(pb1.x);
        Bs[baseB[1] + 2]  = f2tf32(pb1.y);
        Bs[baseB[1] + 4]  = f2tf32(pb1.z);
        Bs[baseB[1] + 6]  = f2tf32(pb1.w);
        __syncthreads();
        if (st + 1 < NST) {
            pa0 = *(const float4*)(aptr0 + (st + 1) * 16);
            pa1 = *(const float4*)(aptr1 + (st + 1) * 16);
            pb0 = *(const float4*)(bptr0 + (st + 1) * 16);
            pb1 = *(const float4*)(bptr1 + (st + 1) * 16);
        }
#pragma unroll
        for (int s = 0; s < 2; s++) {
            uint4 af[4];
            uint2 bf[4];
#pragma unroll
            for (int i = 0; i < 4; i++)
                af[i] = *(const uint4*)&As[(((4 * wm + i) * 2 + s) * 32 + lane) * 4];
#pragma unroll
            for (int j = 0; j < 4; j++)
                bf[j] = *(const uint2*)&Bs[(((4 * wn + j) * 2 + s) * 32 + lane) * 2];
#pragma unroll
            for (int i = 0; i < 4; i++)
#pragma unroll
                for (int j = 0; j < 4; j++)
                    mma_tf32(acc[i][j], (const uint32_t*)&af[i], (const uint32_t*)&bf[j]);
        }
    }
}

// ---------------------------------------------------------------------------
// GEMM1: qkv = x @ W_qkv^T -> scatter into g_q (pre-scaled), g_k, g_v
// grid (24, 64), 256 threads.
// ---------------------------------------------------------------------------
__global__ __launch_bounds__(256) void qkv_gemm_mma(const float* __restrict__ A,
                                                    const float* __restrict__ W) {
    __shared__ uint32_t As[2048];
    __shared__ uint32_t Bs[2048];
    const int m0 = blockIdx.y * 128;
    const int n0 = blockIdx.x * 128;
    float acc[4][4][4];
    tf32_mainloop(A, W, m0, n0, As, Bs, acc);

    const int tid = threadIdx.x;
    const int lane = tid & 31;
    const int wid = tid >> 5;
    const int wm = wid >> 2, wn = wid & 3;

    const int t = n0 >> 10;              // 0=q 1=k 2=v (constant per block)
    const float scale = (t == 0) ? 0.125f : 1.0f;
    float* dst = (t == 0) ? g_q : ((t == 1) ? g_k : g_v);

#pragma unroll
    for (int i = 0; i < 4; i++) {
#pragma unroll
        for (int j = 0; j < 4; j++) {
#pragma unroll
            for (int hh = 0; hh < 2; hh++) {
                const int m = m0 + 64 * wm + 16 * i + (lane >> 2) + 8 * hh;
                const int n = n0 + 32 * wn + 8 * j + 2 * (lane & 3);
                const int b = m >> 10, nn = m & 1023;
                const int e = n & 1023;
                const int h = e >> 6, d = e & 63;
                float2 o;
                o.x = acc[i][j][2 * hh + 0] * scale;
                o.y = acc[i][j][2 * hh + 1] * scale;
                *(float2*)&dst[(((size_t)b * HEADS + h) * NSEQ + nn) * DHEAD + d] = o;
            }
        }
    }
}

// ---------------------------------------------------------------------------
// GEMM2: out = g_att @ W_out^T + b_out; grid (8, 64), 256 threads.
// ---------------------------------------------------------------------------
__global__ __launch_bounds__(256) void out_gemm_mma(const float* __restrict__ W,
                                                    const float* __restrict__ bias,
                                                    float* __restrict__ out) {
    __shared__ uint32_t As[2048];
    __shared__ uint32_t Bs[2048];
    const int m0 = blockIdx.y * 128;
    const int n0 = blockIdx.x * 128;
    float acc[4][4][4];
    tf32_mainloop(g_att, W, m0, n0, As, Bs, acc);

    const int tid = threadIdx.x;
    const int lane = tid & 31;
    const int wid = tid >> 5;
    const int wm = wid >> 2, wn = wid & 3;

#pragma unroll
    for (int i = 0; i < 4; i++) {
#pragma unroll
        for (int j = 0; j < 4; j++) {
#pragma unroll
            for (int hh = 0; hh < 2; hh++) {
                const int m = m0 + 64 * wm + 16 * i + (lane >> 2) + 8 * hh;
                const int n = n0 + 32 * wn + 8 * j + 2 * (lane & 3);
                float2 o;
                o.x = acc[i][j][2 * hh + 0] + bias[n + 0];
                o.y = acc[i][j][2 * hh + 1] + bias[n + 1];
                *(float2*)&out[(size_t)m * EMBD + n] = o;
            }
        }
    }
}

// ---------------------------------------------------------------------------
// Flash-style attention with additive bias gather (R1-proven, unchanged).
// ---------------------------------------------------------------------------
#define PADT 68
#define PADP 65

__global__ __launch_bounds__(256) void attn_kernel(const float* __restrict__ biases,
                                                   const int* __restrict__ idxs) {
    extern __shared__ float sm[];
    float* Qt = sm;
    float* Kt = Qt + 64 * PADT;
    float* Vs = Kt + 64 * PADT;
    float* Pt = Kt;

    const int tid = threadIdx.x;
    const int ty = tid >> 4, tx = tid & 15;
    const int r0 = ty << 2, c0 = tx << 2;
    const int h = blockIdx.y & 15;
    const int b = blockIdx.y >> 4;
    const int i0 = blockIdx.x << 6;

    const size_t bh = (size_t)(b * HEADS + h) * NSEQ * DHEAD;
    const float* qb = g_q + bh;
    const float* kb = g_k + bh;
    const float* vb = g_v + bh;
    const float* brow = biases + h * 1024;

    const int lr = tid & 63;
    const int ld0 = (tid >> 6) << 4;

    {
        const float4* src = (const float4*)(qb + (size_t)(i0 + lr) * DHEAD + ld0);
#pragma unroll
        for (int u = 0; u < 4; u++) {
            float4 t4 = src[u];
            int d = ld0 + (u << 2);
            Qt[(d + 0) * PADT + lr] = t4.x;
            Qt[(d + 1) * PADT + lr] = t4.y;
            Qt[(d + 2) * PADT + lr] = t4.z;
            Qt[(d + 3) * PADT + lr] = t4.w;
        }
    }

    float acc[4][4];
#pragma unroll
    for (int i = 0; i < 4; i++)
#pragma unroll
        for (int j = 0; j < 4; j++) acc[i][j] = 0.f;
    float mrow[4], lrow[4];
#pragma unroll
    for (int i = 0; i < 4; i++) { mrow[i] = -1e30f; lrow[i] = 0.f; }

    for (int j0 = 0; j0 < NSEQ; j0 += 64) {
        __syncthreads();
        {
            const float4* ks = (const float4*)(kb + (size_t)(j0 + lr) * DHEAD + ld0);
#pragma unroll
            for (int u = 0; u < 4; u++) {
                float4 t4 = ks[u];
                int d = ld0 + (u << 2);
                Kt[(d + 0) * PADT + lr] = t4.x;
                Kt[(d + 1) * PADT + lr] = t4.y;
                Kt[(d + 2) * PADT + lr] = t4.z;
                Kt[(d + 3) * PADT + lr] = t4.w;
            }
            const float4* vg = (const float4*)(vb + (size_t)(j0 + lr) * DHEAD + ld0);
            float4* vd = (float4*)&Vs[lr * PADT + ld0];
#pragma unroll
            for (int u = 0; u < 4; u++) vd[u] = vg[u];
        }
        __syncthreads();

        float s[4][4];
#pragma unroll
        for (int i = 0; i < 4; i++)
#pragma unroll
            for (int j = 0; j < 4; j++) s[i][j] = 0.f;
#pragma unroll
        for (int d = 0; d < 64; d++) {
            float4 a4 = *(const float4*)&Qt[d * PADT + r0];
            float4 b4 = *(const float4*)&Kt[d * PADT + c0];
            s[0][0] += a4.x * b4.x; s[0][1] += a4.x * b4.y; s[0][2] += a4.x * b4.z; s[0][3] += a4.x * b4.w;
            s[1][0] += a4.y * b4.x; s[1][1] += a4.y * b4.y; s[1][2] += a4.y * b4.z; s[1][3] += a4.y * b4.w;
            s[2][0] += a4.z * b4.x; s[2][1] += a4.z * b4.y; s[2][2] += a4.z * b4.z; s[2][3] += a4.z * b4.w;
            s[3][0] += a4.w * b4.x; s[3][1] += a4.w * b4.y; s[3][2] += a4.w * b4.z; s[3][3] += a4.w * b4.w;
        }

#pragma unroll
        for (int i = 0; i < 4; i++) {
            const int4 idx4 = *(const int4*)&idxs[(size_t)(i0 + r0 + i) * NSEQ + j0 + c0];
            s[i][0] += __ldg(&brow[idx4.x]);
            s[i][1] += __ldg(&brow[idx4.y]);
            s[i][2] += __ldg(&brow[idx4.z]);
            s[i][3] += __ldg(&brow[idx4.w]);
        }

#pragma unroll
        for (int i = 0; i < 4; i++) {
            float tm = fmaxf(fmaxf(s[i][0], s[i][1]), fmaxf(s[i][2], s[i][3]));
#pragma unroll
            for (int off = 8; off >= 1; off >>= 1)
                tm = fmaxf(tm, __shfl_xor_sync(0xFFFFFFFFu, tm, off));
            const float mnew = fmaxf(mrow[i], tm);
            const float sc = __expf(mrow[i] - mnew);
            mrow[i] = mnew;
            float rs = 0.f;
#pragma unroll
            for (int j = 0; j < 4; j++) {
                s[i][j] = __expf(s[i][j] - mnew);
                rs += s[i][j];
            }
#pragma unroll
            for (int off = 8; off >= 1; off >>= 1)
                rs += __shfl_xor_sync(0xFFFFFFFFu, rs, off);
            lrow[i] = lrow[i] * sc + rs;
#pragma unroll
            for (int j = 0; j < 4; j++) acc[i][j] *= sc;
        }

        __syncthreads();
#pragma unroll
        for (int j = 0; j < 4; j++)
#pragma unroll
            for (int i = 0; i < 4; i++)
                Pt[(c0 + j) * PADP + r0 + i] = s[i][j];
        __syncthreads();

#pragma unroll
        for (int c = 0; c < 64; c++) {
            const float a0 = Pt[c * PADP + r0 + 0];
            const float a1 = Pt[c * PADP + r0 + 1];
            const float a2 = Pt[c * PADP + r0 + 2];
            const float a3 = Pt[c * PADP + r0 + 3];
            const float4 v4 = *(const float4*)&Vs[c * PADT + c0];
            acc[0][0] += a0 * v4.x; acc[0][1] += a0 * v4.y; acc[0][2] += a0 * v4.z; acc[0][3] += a0 * v4.w;
            acc[1][0] += a1 * v4.x; acc[1][1] += a1 * v4.y; acc[1][2] += a1 * v4.z; acc[1][3] += a1 * v4.w;
            acc[2][0] += a2 * v4.x; acc[2][1] += a2 * v4.y; acc[2][2] += a2 * v4.z; acc[2][3] += a2 * v4.w;
            acc[3][0] += a3 * v4.x; acc[3][1] += a3 * v4.y; acc[3][2] += a3 * v4.z; acc[3][3] += a3 * v4.w;
        }
    }

#pragma unroll
    for (int i = 0; i < 4; i++) {
        const float inv = 1.f / lrow[i];
        float4 o;
        o.x = acc[i][0] * inv;
        o.y = acc[i][1] * inv;
        o.z = acc[i][2] * inv;
        o.w = acc[i][3] * inv;
        *(float4*)&g_att[((size_t)(b * NSEQ) + i0 + r0 + i) * EMBD + h * DHEAD + c0] = o;
    }
}

// ---------------------------------------------------------------------------
extern "C" void kernel_launch(void* const* d_in, const int* in_sizes, int n_in,
                              void* d_out, int out_size) {
    (void)in_sizes; (void)n_in; (void)out_size;
    const float* x      = (const float*)d_in[0];
    const float* W_qkv  = (const float*)d_in[1];
    const float* biases = (const float*)d_in[2];
    const int*   idxs   = (const int*)d_in[3];
    const float* W_out  = (const float*)d_in[4];
    const float* b_out  = (const float*)d_in[5];
    float* out = (float*)d_out;

    const int attn_smem = 3 * 64 * PADT * (int)sizeof(float);
    cudaFuncSetAttribute(attn_kernel, cudaFuncAttributeMaxDynamicSharedMemorySize, attn_smem);

    qkv_gemm_mma<<<dim3(24, 64), 256>>>(x, W_qkv);
    attn_kernel<<<dim3(16, BATCHX * HEADS), 256, attn_smem>>>(biases, idxs);
    out_gemm_mma<<<dim3(8, 64), 256>>>(W_out, b_out, out);
}

// round 4
// speedup vs baseline: 2.4431x; 2.4431x over previous
#include <cuda_runtime.h>
#include <cstdint>

// Problem constants
#define BATCHX 8
#define NSEQ   1024
#define EMBD   1024
#define HEADS  16
#define DHEAD  64
#define KDIM   1024
#define MROWS  (BATCHX * NSEQ)   // 8192

// Scratch (device globals: allocation-free per harness rules)
__device__ float g_q[BATCHX * HEADS * NSEQ * DHEAD];
__device__ float g_k[BATCHX * HEADS * NSEQ * DHEAD];
__device__ float g_v[BATCHX * HEADS * NSEQ * DHEAD];
__device__ float g_att[MROWS * EMBD];

__device__ __forceinline__ uint32_t f2tf32(float x) {
    uint32_t y;
    asm("cvt.rna.tf32.f32 %0, %1;" : "=r"(y) : "f"(x));
    return y;
}

__device__ __forceinline__ void mma_tf32(float* c, const uint32_t* a, const uint32_t* b) {
    asm volatile(
        "mma.sync.aligned.m16n8k8.row.col.f32.tf32.tf32.f32 "
        "{%0,%1,%2,%3}, {%4,%5,%6,%7}, {%8,%9}, {%0,%1,%2,%3};"
        : "+f"(c[0]), "+f"(c[1]), "+f"(c[2]), "+f"(c[3])
        : "r"(a[0]), "r"(a[1]), "r"(a[2]), "r"(a[3]), "r"(b[0]), "r"(b[1]));
}

// ===========================================================================
// tf32 warp-MMA GEMM, DOUBLE-BUFFERED. C[m,n] = sum_k A[m,k]*B[n,k].
// Block 128x128, BK=16, 256 thr, 8 warps (2 M x 4 N), warp tile 64x32.
// SMEM in fragment order; one __syncthreads per K-stage.
// ===========================================================================
__device__ __forceinline__ void tf32_mainloop_db(const float* __restrict__ A,
                                                 const float* __restrict__ B,
                                                 int m0, int n0,
                                                 uint32_t (*As)[2048],
                                                 uint32_t (*Bs)[2048],
                                                 float acc[4][4][4]) {
    const int tid = threadIdx.x;
    const int lane = tid & 31;
    const int wid = tid >> 5;
    const int wm = wid >> 2, wn = wid & 3;

    const int lrow = tid >> 2;        // 0..63 (+64 for second slot)
    const int lkb = tid & 3;
    int baseA[2], baseB[2];
#pragma unroll
    for (int i = 0; i < 2; i++) {
        const int row = lrow + 64 * i;
        const int t = row >> 4, mi = row & 15;
        const int s = lkb >> 1;
        const int rA = (mi >> 3) + 2 * (lkb & 1);
        baseA[i] = ((t * 2 + s) * 32 + (mi & 7) * 4) * 4 + rA;
        const int u = row >> 3, ni = row & 7;
        baseB[i] = ((u * 2 + s) * 32 + ni * 4) * 2 + (lkb & 1);
    }
    const float* aptr0 = A + (size_t)(m0 + lrow) * KDIM + lkb * 4;
    const float* aptr1 = aptr0 + (size_t)64 * KDIM;
    const float* bptr0 = B + (size_t)(n0 + lrow) * KDIM + lkb * 4;
    const float* bptr1 = bptr0 + (size_t)64 * KDIM;

#pragma unroll
    for (int i = 0; i < 4; i++)
#pragma unroll
        for (int j = 0; j < 4; j++)
#pragma unroll
            for (int r = 0; r < 4; r++) acc[i][j][r] = 0.f;

    // Preload stage 0 into buffer 0
    {
        float4 pa0 = *(const float4*)aptr0;
        float4 pa1 = *(const float4*)aptr1;
        float4 pb0 = *(const float4*)bptr0;
        float4 pb1 = *(const float4*)bptr1;
        As[0][baseA[0] + 0]  = f2tf32(pa0.x);
        As[0][baseA[0] + 4]  = f2tf32(pa0.y);
        As[0][baseA[0] + 8]  = f2tf32(pa0.z);
        As[0][baseA[0] + 12] = f2tf32(pa0.w);
        As[0][baseA[1] + 0]  = f2tf32(pa1.x);
        As[0][baseA[1] + 4]  = f2tf32(pa1.y);
        As[0][baseA[1] + 8]  = f2tf32(pa1.z);
        As[0][baseA[1] + 12] = f2tf32(pa1.w);
        Bs[0][baseB[0] + 0]  = f2tf32(pb0.x);
        Bs[0][baseB[0] + 2]  = f2tf32(pb0.y);
        Bs[0][baseB[0] + 4]  = f2tf32(pb0.z);
        Bs[0][baseB[0] + 6]  = f2tf32(pb0.w);
        Bs[0][baseB[1] + 0]  = f2tf32(pb1.x);
        Bs[0][baseB[1] + 2]  = f2tf32(pb1.y);
        Bs[0][baseB[1] + 4]  = f2tf32(pb1.z);
        Bs[0][baseB[1] + 6]  = f2tf32(pb1.w);
    }
    __syncthreads();

    const int NST = KDIM / 16;   // 64 stages
    for (int st = 0; st < NST; st++) {
        const int cur = st & 1;
        float4 pa0, pa1, pb0, pb1;
        const bool more = (st + 1 < NST);
        if (more) {
            pa0 = *(const float4*)(aptr0 + (st + 1) * 16);
            pa1 = *(const float4*)(aptr1 + (st + 1) * 16);
            pb0 = *(const float4*)(bptr0 + (st + 1) * 16);
            pb1 = *(const float4*)(bptr1 + (st + 1) * 16);
        }
        // Compute this stage while prefetch LDGs are in flight
#pragma unroll
        for (int s = 0; s < 2; s++) {
            uint4 af[4];
            uint2 bf[4];
#pragma unroll
            for (int i = 0; i < 4; i++)
                af[i] = *(const uint4*)&As[cur][(((4 * wm + i) * 2 + s) * 32 + lane) * 4];
#pragma unroll
            for (int j = 0; j < 4; j++)
                bf[j] = *(const uint2*)&Bs[cur][(((4 * wn + j) * 2 + s) * 32 + lane) * 2];
#pragma unroll
            for (int i = 0; i < 4; i++)
#pragma unroll
                for (int j = 0; j < 4; j++)
                    mma_tf32(acc[i][j], (const uint32_t*)&af[i], (const uint32_t*)&bf[j]);
        }
        if (more) {
            const int nxt = cur ^ 1;
            As[nxt][baseA[0] + 0]  = f2tf32(pa0.x);
            As[nxt][baseA[0] + 4]  = f2tf32(pa0.y);
            As[nxt][baseA[0] + 8]  = f2tf32(pa0.z);
            As[nxt][baseA[0] + 12] = f2tf32(pa0.w);
            As[nxt][baseA[1] + 0]  = f2tf32(pa1.x);
            As[nxt][baseA[1] + 4]  = f2tf32(pa1.y);
            As[nxt][baseA[1] + 8]  = f2tf32(pa1.z);
            As[nxt][baseA[1] + 12] = f2tf32(pa1.w);
            Bs[nxt][baseB[0] + 0]  = f2tf32(pb0.x);
            Bs[nxt][baseB[0] + 2]  = f2tf32(pb0.y);
            Bs[nxt][baseB[0] + 4]  = f2tf32(pb0.z);
            Bs[nxt][baseB[0] + 6]  = f2tf32(pb0.w);
            Bs[nxt][baseB[1] + 0]  = f2tf32(pb1.x);
            Bs[nxt][baseB[1] + 2]  = f2tf32(pb1.y);
            Bs[nxt][baseB[1] + 4]  = f2tf32(pb1.z);
            Bs[nxt][baseB[1] + 6]  = f2tf32(pb1.w);
        }
        __syncthreads();
    }
}

// ---------------------------------------------------------------------------
// GEMM1: qkv = x @ W_qkv^T -> scatter into g_q (pre-scaled), g_k, g_v
// ---------------------------------------------------------------------------
__global__ __launch_bounds__(256) void qkv_gemm_mma(const float* __restrict__ A,
                                                    const float* __restrict__ W) {
    __shared__ uint32_t As[2][2048];
    __shared__ uint32_t Bs[2][2048];
    const int m0 = blockIdx.y * 128;
    const int n0 = blockIdx.x * 128;
    float acc[4][4][4];
    tf32_mainloop_db(A, W, m0, n0, As, Bs, acc);

    const int tid = threadIdx.x;
    const int lane = tid & 31;
    const int wid = tid >> 5;
    const int wm = wid >> 2, wn = wid & 3;

    const int t = n0 >> 10;              // 0=q 1=k 2=v (constant per block)
    const float scale = (t == 0) ? 0.125f : 1.0f;
    float* dst = (t == 0) ? g_q : ((t == 1) ? g_k : g_v);

#pragma unroll
    for (int i = 0; i < 4; i++) {
#pragma unroll
        for (int j = 0; j < 4; j++) {
#pragma unroll
            for (int hh = 0; hh < 2; hh++) {
                const int m = m0 + 64 * wm + 16 * i + (lane >> 2) + 8 * hh;
                const int n = n0 + 32 * wn + 8 * j + 2 * (lane & 3);
                const int b = m >> 10, nn = m & 1023;
                const int e = n & 1023;
                const int h = e >> 6, d = e & 63;
                float2 o;
                o.x = acc[i][j][2 * hh + 0] * scale;
                o.y = acc[i][j][2 * hh + 1] * scale;
                *(float2*)&dst[(((size_t)b * HEADS + h) * NSEQ + nn) * DHEAD + d] = o;
            }
        }
    }
}

// ---------------------------------------------------------------------------
// GEMM2: out = g_att @ W_out^T + b_out
// ---------------------------------------------------------------------------
__global__ __launch_bounds__(256) void out_gemm_mma(const float* __restrict__ W,
                                                    const float* __restrict__ bias,
                                                    float* __restrict__ out) {
    __shared__ uint32_t As[2][2048];
    __shared__ uint32_t Bs[2][2048];
    const int m0 = blockIdx.y * 128;
    const int n0 = blockIdx.x * 128;
    float acc[4][4][4];
    tf32_mainloop_db(g_att, W, m0, n0, As, Bs, acc);

    const int tid = threadIdx.x;
    const int lane = tid & 31;
    const int wid = tid >> 5;
    const int wm = wid >> 2, wn = wid & 3;

#pragma unroll
    for (int i = 0; i < 4; i++) {
#pragma unroll
        for (int j = 0; j < 4; j++) {
#pragma unroll
            for (int hh = 0; hh < 2; hh++) {
                const int m = m0 + 64 * wm + 16 * i + (lane >> 2) + 8 * hh;
                const int n = n0 + 32 * wn + 8 * j + 2 * (lane & 3);
                float2 o;
                o.x = acc[i][j][2 * hh + 0] + bias[n + 0];
                o.y = acc[i][j][2 * hh + 1] + bias[n + 1];
                *(float2*)&out[(size_t)m * EMBD + n] = o;
            }
        }
    }
}

// ===========================================================================
// Tensor-core flash attention (tf32 mma.sync), FA-2 structure.
// CTA: 256 thr (8 warps), Q tile 128 rows (warp w owns rows 16w..16w+15),
// key tile 64. SMEM (u32, fragment order):
//   Qf[8192] (Q, a-frag), Kf[4096] (K, b-frag), Vf[4096] (V^T, b-frag),
//   Pf[8192] (P, a-frag; warp-private row blocks). Total 96KB.
// ===========================================================================
__global__ __launch_bounds__(256) void attn_mma(const float* __restrict__ biases,
                                                const int* __restrict__ idxs) {
    extern __shared__ uint32_t smu[];
    uint32_t* Qf = smu;             // 8192
    uint32_t* Kf = smu + 8192;      // 4096
    uint32_t* Vf = smu + 12288;     // 4096
    uint32_t* Pf = smu + 16384;     // 8192

    const int tid = threadIdx.x;
    const int lane = tid & 31;
    const int w = tid >> 5;
    const int g = lane >> 2;        // row-in-8 group
    const int tig = lane & 3;

    const int q0 = blockIdx.x << 7;             // 128-row Q tile
    const int h = blockIdx.y & 15;
    const int b = blockIdx.y >> 4;

    const size_t bh = (size_t)(b * HEADS + h) * NSEQ * DHEAD;
    const float* qb = g_q + bh;
    const float* kb = g_k + bh;
    const float* vb = g_v + bh;
    const float* brow = biases + h * 1024;

    // ---- Load Q tile into a-frag order (done once) ----
#pragma unroll
    for (int i = 0; i < 8; i++) {
        const int slot = tid + 256 * i;
        const int row = slot >> 4;       // 0..127
        const int f4 = slot & 15;
        const float4 qv = *(const float4*)(qb + (size_t)(q0 + row) * DHEAD + f4 * 4);
        const int t = row >> 4, mi = row & 15;
        const int s = f4 >> 1;
        const int reg = (mi >> 3) + 2 * (f4 & 1);
        const int lbase = (t * 8 + s) * 32 + 4 * (mi & 7);
        Qf[(lbase + 0) * 4 + reg] = f2tf32(qv.x);
        Qf[(lbase + 1) * 4 + reg] = f2tf32(qv.y);
        Qf[(lbase + 2) * 4 + reg] = f2tf32(qv.z);
        Qf[(lbase + 3) * 4 + reg] = f2tf32(qv.w);
    }

    float oc[8][4];
#pragma unroll
    for (int u = 0; u < 8; u++)
#pragma unroll
        for (int r = 0; r < 4; r++) oc[u][r] = 0.f;
    float mrow[2] = {-1e30f, -1e30f};
    float lrow[2] = {0.f, 0.f};

    const int* ip0 = idxs + (size_t)(q0 + 16 * w + g) * NSEQ;
    const int* ip1 = ip0 + 8 * NSEQ;

    for (int j0 = 0; j0 < NSEQ; j0 += 64) {
        __syncthreads();   // prev PV done reading Vf; (1st iter: nothing)
        // ---- Load K (b-frag for QK) and V (b-frag for PV) tiles ----
#pragma unroll
        for (int i = 0; i < 4; i++) {
            const int slot = tid + 256 * i;
            const int key = slot >> 4;     // 0..63
            const int f4 = slot & 15;
            const float4 kv = *(const float4*)(kb + (size_t)(j0 + key) * DHEAD + f4 * 4);
            {
                const int u = key >> 3, n = key & 7;
                const int s = f4 >> 1;
                const int reg = f4 & 1;
                const int lbase = (u * 8 + s) * 32 + 4 * n;
                Kf[(lbase + 0) * 2 + reg] = f2tf32(kv.x);
                Kf[(lbase + 1) * 2 + reg] = f2tf32(kv.y);
                Kf[(lbase + 2) * 2 + reg] = f2tf32(kv.z);
                Kf[(lbase + 3) * 2 + reg] = f2tf32(kv.w);
            }
            const float4 vv = *(const float4*)(vb + (size_t)(j0 + key) * DHEAD + f4 * 4);
            {
                // element (d = 4*f4+e, key): u2=d>>3, n2=d&7, s2=key>>3, kk2=key&7
                const int u2 = f4 >> 1;
                const int s2 = key >> 3;
                const int r2 = (key & 7) >> 2;
                const int l2 = (u2 * 8 + s2) * 32 + 16 * (f4 & 1) + (key & 3);
                Vf[(l2 + 0) * 2 + r2]  = f2tf32(vv.x);
                Vf[(l2 + 4) * 2 + r2]  = f2tf32(vv.y);
                Vf[(l2 + 8) * 2 + r2]  = f2tf32(vv.z);
                Vf[(l2 + 12) * 2 + r2] = f2tf32(vv.w);
            }
        }
        __syncthreads();   // K/V (and Qf on 1st iter) ready

        // ---- S = Q K^T (per-warp 16x64) ----
        float sc[8][4];
#pragma unroll
        for (int u = 0; u < 8; u++)
#pragma unroll
            for (int r = 0; r < 4; r++) sc[u][r] = 0.f;
#pragma unroll
        for (int s = 0; s < 8; s++) {
            const uint4 a = *(const uint4*)&Qf[((w * 8 + s) * 32 + lane) * 4];
#pragma unroll
            for (int u = 0; u < 8; u++) {
                const uint2 bb = *(const uint2*)&Kf[((u * 8 + s) * 32 + lane) * 2];
                mma_tf32(sc[u], (const uint32_t*)&a, (const uint32_t*)&bb);
            }
        }

        // ---- bias add (fp32 gather) ----
#pragma unroll
        for (int u = 0; u < 8; u++) {
            const int cc = j0 + 8 * u + 2 * tig;
            const int2 i0 = *(const int2*)(ip0 + cc);
            const int2 i1 = *(const int2*)(ip1 + cc);
            sc[u][0] += __ldg(&brow[i0.x]);
            sc[u][1] += __ldg(&brow[i0.y]);
            sc[u][2] += __ldg(&brow[i1.x]);
            sc[u][3] += __ldg(&brow[i1.y]);
        }

        // ---- online softmax (rows g and g+8; 4-lane shfl reductions) ----
#pragma unroll
        for (int a2 = 0; a2 < 2; a2++) {
            float mx = -1e30f;
#pragma unroll
            for (int u = 0; u < 8; u++)
                mx = fmaxf(mx, fmaxf(sc[u][2 * a2], sc[u][2 * a2 + 1]));
            mx = fmaxf(mx, __shfl_xor_sync(0xFFFFFFFFu, mx, 1));
            mx = fmaxf(mx, __shfl_xor_sync(0xFFFFFFFFu, mx, 2));
            const float mnew = fmaxf(mrow[a2], mx);
            const float resc = __expf(mrow[a2] - mnew);
            mrow[a2] = mnew;
            float rs = 0.f;
#pragma unroll
            for (int u = 0; u < 8; u++) {
                sc[u][2 * a2]     = __expf(sc[u][2 * a2] - mnew);
                sc[u][2 * a2 + 1] = __expf(sc[u][2 * a2 + 1] - mnew);
                rs += sc[u][2 * a2] + sc[u][2 * a2 + 1];
            }
            rs += __shfl_xor_sync(0xFFFFFFFFu, rs, 1);
            rs += __shfl_xor_sync(0xFFFFFFFFu, rs, 2);
            lrow[a2] = lrow[a2] * resc + rs;
#pragma unroll
            for (int u = 0; u < 8; u++) {
                oc[u][2 * a2]     *= resc;
                oc[u][2 * a2 + 1] *= resc;
            }
        }

        // ---- store P (c-frag -> a-frag permute; warp-private rows) ----
        {
            const int rlo = 2 * (tig >> 1);
            const int lc0 = 4 * g + ((2 * tig) & 3);
            const int lc1 = 4 * g + ((2 * tig + 1) & 3);
#pragma unroll
            for (int u = 0; u < 8; u++) {
                const int base = ((w * 8 + u) * 32) * 4;
                Pf[base + lc0 * 4 + rlo]     = f2tf32(sc[u][0]);
                Pf[base + lc1 * 4 + rlo]     = f2tf32(sc[u][1]);
                Pf[base + lc0 * 4 + rlo + 1] = f2tf32(sc[u][2]);
                Pf[base + lc1 * 4 + rlo + 1] = f2tf32(sc[u][3]);
            }
        }
        __syncwarp();

        // ---- O += P V ----
#pragma unroll
        for (int s = 0; s < 8; s++) {
            const uint4 a = *(const uint4*)&Pf[((w * 8 + s) * 32 + lane) * 4];
#pragma unroll
            for (int u2 = 0; u2 < 8; u2++) {
                const uint2 bb = *(const uint2*)&Vf[((u2 * 8 + s) * 32 + lane) * 2];
                mma_tf32(oc[u2], (const uint32_t*)&a, (const uint32_t*)&bb);
            }
        }
    }

    // ---- normalize + write (head-merged layout for out-proj) ----
    const float inv0 = 1.f / lrow[0];
    const float inv1 = 1.f / lrow[1];
    const int row0 = q0 + 16 * w + g;
#pragma unroll
    for (int u2 = 0; u2 < 8; u2++) {
        const int d = 8 * u2 + 2 * tig;
        float2 o0, o1;
        o0.x = oc[u2][0] * inv0; o0.y = oc[u2][1] * inv0;
        o1.x = oc[u2][2] * inv1; o1.y = oc[u2][3] * inv1;
        *(float2*)&g_att[((size_t)b * NSEQ + row0) * EMBD + h * DHEAD + d] = o0;
        *(float2*)&g_att[((size_t)b * NSEQ + row0 + 8) * EMBD + h * DHEAD + d] = o1;
    }
}

// ---------------------------------------------------------------------------
extern "C" void kernel_launch(void* const* d_in, const int* in_sizes, int n_in,
                              void* d_out, int out_size) {
    (void)in_sizes; (void)n_in; (void)out_size;
    const float* x      = (const float*)d_in[0];
    const float* W_qkv  = (const float*)d_in[1];
    const float* biases = (const float*)d_in[2];
    const int*   idxs   = (const int*)d_in[3];
    const float* W_out  = (const float*)d_in[4];
    const float* b_out  = (const float*)d_in[5];
    float* out = (float*)d_out;

    const int attn_smem = 24576 * (int)sizeof(uint32_t);   // 96 KB
    cudaFuncSetAttribute(attn_mma, cudaFuncAttributeMaxDynamicSharedMemorySize,
                         attn_smem);

    qkv_gemm_mma<<<dim3(24, 64), 256>>>(x, W_qkv);
    attn_mma<<<dim3(8, BATCHX * HEADS), 256, attn_smem>>>(biases, idxs);
    out_gemm_mma<<<dim3(8, 64), 256>>>(W_out, b_out, out);
}

// round 5
// speedup vs baseline: 3.5243x; 1.4425x over previous
#include <cuda_runtime.h>
#include <cstdint>

// Problem constants
#define BATCHX 8
#define NSEQ   1024
#define EMBD   1024
#define HEADS  16
#define DHEAD  64
#define KDIM   1024
#define MROWS  (BATCHX * NSEQ)   // 8192

// Scratch (device globals: allocation-free per harness rules)
__device__ float g_q[BATCHX * HEADS * NSEQ * DHEAD];
__device__ float g_k[BATCHX * HEADS * NSEQ * DHEAD];
__device__ float g_v[BATCHX * HEADS * NSEQ * DHEAD];
__device__ float g_att[MROWS * EMBD];
__device__ float g_xr[MROWS * EMBD];          // tf32-rounded x
__device__ float g_wqr[3 * EMBD * EMBD];      // tf32-rounded W_qkv
__device__ float g_wor[EMBD * EMBD];          // tf32-rounded W_out

__device__ __forceinline__ uint32_t smem_u32(const void* p) {
    uint32_t a;
    asm("{ .reg .u64 t; cvta.to.shared.u64 t, %1; cvt.u32.u64 %0, t; }"
        : "=r"(a) : "l"(p));
    return a;
}

__device__ __forceinline__ uint32_t f2tf32(float x) {
    uint32_t y;
    asm("cvt.rna.tf32.f32 %0, %1;" : "=r"(y) : "f"(x));
    return y;
}

__device__ __forceinline__ void mma_tf32(float* c, const uint32_t* a, const uint32_t* b) {
    asm volatile(
        "mma.sync.aligned.m16n8k8.row.col.f32.tf32.tf32.f32 "
        "{%0,%1,%2,%3}, {%4,%5,%6,%7}, {%8,%9}, {%0,%1,%2,%3};"
        : "+f"(c[0]), "+f"(c[1]), "+f"(c[2]), "+f"(c[3])
        : "r"(a[0]), "r"(a[1]), "r"(a[2]), "r"(a[3]), "r"(b[0]), "r"(b[1]));
}

__device__ __forceinline__ void ldsm4(uint32_t* r, uint32_t addr) {
    asm volatile("ldmatrix.sync.aligned.m8n8.x4.shared.b16 {%0,%1,%2,%3}, [%4];"
                 : "=r"(r[0]), "=r"(r[1]), "=r"(r[2]), "=r"(r[3]) : "r"(addr));
}

__device__ __forceinline__ void cpa16(uint32_t dst, const void* src) {
    asm volatile("cp.async.cg.shared.global [%0], [%1], 16;" :: "r"(dst), "l"(src));
}

// ---------------------------------------------------------------------------
// tf32 pre-round pass (enables cvt-free cp.async staging in the GEMMs)
// ---------------------------------------------------------------------------
__global__ __launch_bounds__(256) void tf32_round_kernel(const float4* __restrict__ s,
                                                         float4* __restrict__ d, int n4) {
    const int i = blockIdx.x * 256 + threadIdx.x;
    if (i < n4) {
        const float4 v = s[i];
        uint4 w;
        w.x = f2tf32(v.x); w.y = f2tf32(v.y); w.z = f2tf32(v.z); w.w = f2tf32(v.w);
        d[i] = *(const float4*)&w;
    }
}

// ===========================================================================
// tf32 GEMM: cp.async 3-stage ring + ldmatrix frag loads.
// Block 128x128, BK=16, 256 thr, 8 warps (2 M x 4 N), warp tile 64x32.
// Tile rows are 64B (4 x 16B units), unit XOR-swizzled: u ^= (row^(row>>2))&3.
// ===========================================================================
#define STG_BYTES 16384   // per stage: A 8KB + B 8KB

__device__ __forceinline__ uint32_t offA(int row, int u) {
    return (uint32_t)(row * 64 + ((u ^ ((row ^ (row >> 2)) & 3)) << 4));
}

__device__ __forceinline__ void tf32_mainloop_ca(const float* __restrict__ A,
                                                 const float* __restrict__ B,
                                                 int m0, int n0, char* sm,
                                                 float acc[4][4][4]) {
    const int tid = threadIdx.x;
    const int lane = tid & 31;
    const int wid = tid >> 5;
    const int wm = wid >> 2, wn = wid & 3;
    const uint32_t sb = smem_u32(sm);

    // loader mapping: row = tid>>2 (+64), unit = tid&3
    const int lrow = tid >> 2, lu = tid & 3;
    const uint32_t oA0 = offA(lrow, lu);
    const uint32_t oA1 = offA(lrow + 64, lu);
    const float* ap0 = A + (size_t)(m0 + lrow) * KDIM + lu * 4;
    const float* ap1 = ap0 + (size_t)64 * KDIM;
    const float* bp0 = B + (size_t)(n0 + lrow) * KDIM + lu * 4;
    const float* bp1 = bp0 + (size_t)64 * KDIM;

#pragma unroll
    for (int i = 0; i < 4; i++)
#pragma unroll
        for (int j = 0; j < 4; j++)
#pragma unroll
            for (int r = 0; r < 4; r++) acc[i][j][r] = 0.f;

    // ldmatrix lane constants
    const int sub = lane >> 3;
    const int arow = 64 * wm + (lane & 7) + ((sub & 1) << 3);   // + 16*i
    const int aub = sub >> 1;                                   // + 2*s
    const int brow = 32 * wn + (lane & 7) + ((sub >> 1) << 3);  // + 16*jj
    const int bub = sub & 1;
    const int asw = (arow ^ (arow >> 2)) & 3;   // invariant under +16*i
    const int bsw = (brow ^ (brow >> 2)) & 3;

#define G_ISSUE(st, p)                                                         \
    do {                                                                       \
        const int ko = (st) * 16;                                              \
        const uint32_t bb_ = sb + (uint32_t)(p) * STG_BYTES;                   \
        cpa16(bb_ + oA0, ap0 + ko);                                            \
        cpa16(bb_ + oA1, ap1 + ko);                                            \
        cpa16(bb_ + 8192 + oA0, bp0 + ko);                                     \
        cpa16(bb_ + 8192 + oA1, bp1 + ko);                                     \
    } while (0)

    G_ISSUE(0, 0);
    asm volatile("cp.async.commit_group;");
    G_ISSUE(1, 1);
    asm volatile("cp.async.commit_group;");

    const int NST = KDIM / 16;   // 64
    int p = 0;
    for (int st = 0; st < NST; st++) {
        asm volatile("cp.async.wait_group 1;");
        __syncthreads();
        const uint32_t abase = sb + (uint32_t)p * STG_BYTES;
        const uint32_t bbase = abase + 8192;
#pragma unroll
        for (int s = 0; s < 2; s++) {
            uint32_t af[4][4];
            uint32_t bf[4][2];
#pragma unroll
            for (int i = 0; i < 4; i++) {
                const int row = arow + 16 * i;
                ldsm4(af[i], abase + (uint32_t)(row * 64 + (((2 * s + aub) ^ asw) << 4)));
            }
#pragma unroll
            for (int jj = 0; jj < 2; jj++) {
                uint32_t t[4];
                const int row = brow + 16 * jj;
                ldsm4(t, bbase + (uint32_t)(row * 64 + (((2 * s + bub) ^ bsw) << 4)));
                bf[2 * jj][0] = t[0]; bf[2 * jj][1] = t[1];
                bf[2 * jj + 1][0] = t[2]; bf[2 * jj + 1][1] = t[3];
            }
#pragma unroll
            for (int i = 0; i < 4; i++)
#pragma unroll
                for (int j = 0; j < 4; j++)
                    mma_tf32(acc[i][j], af[i], bf[j]);
        }
        const int nx = st + 2;
        if (nx < NST) G_ISSUE(nx, (nx) % 3);
        asm volatile("cp.async.commit_group;");
        p = (p + 1) % 3;
    }
#undef G_ISSUE
}

// ---------------------------------------------------------------------------
// GEMM1: qkv = xr @ Wqkv_r^T -> scatter into g_q (pre-scaled, tf32-rounded),
// g_k, g_v (tf32-rounded for cvt-free attention staging).
// ---------------------------------------------------------------------------
__global__ __launch_bounds__(256) void qkv_gemm_mma(const float* __restrict__ A,
                                                    const float* __restrict__ W) {
    extern __shared__ char smg[];
    const int m0 = blockIdx.y * 128;
    const int n0 = blockIdx.x * 128;
    float acc[4][4][4];
    tf32_mainloop_ca(A, W, m0, n0, smg, acc);

    const int tid = threadIdx.x;
    const int lane = tid & 31;
    const int wid = tid >> 5;
    const int wm = wid >> 2, wn = wid & 3;

    const int t = n0 >> 10;              // 0=q 1=k 2=v
    const float scale = (t == 0) ? 0.125f : 1.0f;
    float* dst = (t == 0) ? g_q : ((t == 1) ? g_k : g_v);

#pragma unroll
    for (int i = 0; i < 4; i++) {
#pragma unroll
        for (int j = 0; j < 4; j++) {
#pragma unroll
            for (int hh = 0; hh < 2; hh++) {
                const int m = m0 + 64 * wm + 16 * i + (lane >> 2) + 8 * hh;
                const int n = n0 + 32 * wn + 8 * j + 2 * (lane & 3);
                const int b = m >> 10, nn = m & 1023;
                const int e = n & 1023;
                const int h = e >> 6, d = e & 63;
                float2 o;
                o.x = __uint_as_float(f2tf32(acc[i][j][2 * hh + 0] * scale));
                o.y = __uint_as_float(f2tf32(acc[i][j][2 * hh + 1] * scale));
                *(float2*)&dst[(((size_t)b * HEADS + h) * NSEQ + nn) * DHEAD + d] = o;
            }
        }
    }
}

// ---------------------------------------------------------------------------
// GEMM2: out = g_att @ Wout_r^T + b_out  (g_att already tf32-rounded)
// ---------------------------------------------------------------------------
__global__ __launch_bounds__(256) void out_gemm_mma(const float* __restrict__ W,
                                                    const float* __restrict__ bias,
                                                    float* __restrict__ out) {
    extern __shared__ char smg[];
    const int m0 = blockIdx.y * 128;
    const int n0 = blockIdx.x * 128;
    float acc[4][4][4];
    tf32_mainloop_ca(g_att, W, m0, n0, smg, acc);

    const int tid = threadIdx.x;
    const int lane = tid & 31;
    const int wid = tid >> 5;
    const int wm = wid >> 2, wn = wid & 3;

#pragma unroll
    for (int i = 0; i < 4; i++) {
#pragma unroll
        for (int j = 0; j < 4; j++) {
#pragma unroll
            for (int hh = 0; hh < 2; hh++) {
                const int m = m0 + 64 * wm + 16 * i + (lane >> 2) + 8 * hh;
                const int n = n0 + 32 * wn + 8 * j + 2 * (lane & 3);
                float2 o;
                o.x = acc[i][j][2 * hh + 0] + bias[n + 0];
                o.y = acc[i][j][2 * hh + 1] + bias[n + 1];
                *(float2*)&out[(size_t)m * EMBD + n] = o;
            }
        }
    }
}

// ===========================================================================
// Tensor-core flash attention: cp.async staging + ldmatrix fragments.
// CTA 256 thr (8 warps), Q tile 128 rows (warp w owns rows 16w..16w+15),
// key tile 64. SMEM byte map (rows are 256B = 16 swizzled 16B units):
//   Qs 0..32KB  Ks 32..48KB  VT 48..64KB  Ps 64..96KB
// ===========================================================================
#define ATT_Q 0u
#define ATT_K 32768u
#define ATT_V 49152u
#define ATT_P 65536u
#define ATT_SMEM 98304

__device__ __forceinline__ uint32_t off8(int row, int u) {
    return (uint32_t)(row * 256 + ((u ^ (row & 7)) << 4));
}

__global__ __launch_bounds__(256) void attn_mma(const float* __restrict__ biases,
                                                const int* __restrict__ idxs) {
    extern __shared__ char smc[];
    const uint32_t sb = smem_u32(smc);
    const int tid = threadIdx.x;
    const int lane = tid & 31;
    const int w = tid >> 5;
    const int g = lane >> 2;
    const int tig = lane & 3;

    const int q0 = blockIdx.x << 7;
    const int h = blockIdx.y & 15;
    const int b = blockIdx.y >> 4;

    const size_t bh = (size_t)(b * HEADS + h) * NSEQ * DHEAD;
    const float* qb = g_q + bh;
    const float* kb = g_k + bh;
    const float* vb = g_v + bh;
    const float* brow = biases + h * 1024;

    // ---- Q tile via cp.async (once): 128 rows x 16 units ----
#pragma unroll
    for (int i = 0; i < 8; i++) {
        const int slot = tid + 256 * i;
        const int row = slot >> 4, lu = slot & 15;
        cpa16(sb + ATT_Q + off8(row, lu), qb + (size_t)(q0 + row) * DHEAD + lu * 4);
    }
    asm volatile("cp.async.commit_group;");

    float oc[8][4];
#pragma unroll
    for (int u = 0; u < 8; u++)
#pragma unroll
        for (int r = 0; r < 4; r++) oc[u][r] = 0.f;
    float mrow[2] = {-1e30f, -1e30f};
    float lrow[2] = {0.f, 0.f};

    const int* ip0 = idxs + (size_t)(q0 + 16 * w + g) * NSEQ;
    const int* ip1 = ip0 + 8 * NSEQ;

    // ldmatrix lane constants
    const int sub = lane >> 3;
    const int qrow = 16 * w + (lane & 7) + ((sub & 1) << 3);   // A rows (QK & PV)
    const int aub = sub >> 1;
    const int brow_b = (lane & 7) + ((sub >> 1) << 3);          // + 16*jj (B frags)
    const int bub = sub & 1;
    const int qsw = qrow & 7;

    for (int j0 = 0; j0 < NSEQ; j0 += 64) {
        __syncthreads();   // prev iter done with Ks/VT
        // ---- K tile via cp.async: 64 rows x 16 units ----
#pragma unroll
        for (int i = 0; i < 4; i++) {
            const int slot = tid + 256 * i;
            const int row = slot >> 4, lu = slot & 15;
            cpa16(sb + ATT_K + off8(row, lu), kb + (size_t)(j0 + row) * DHEAD + lu * 4);
        }
        asm volatile("cp.async.commit_group;");
        // ---- V transpose into VT[d][key] (register transpose, scalar STS) ----
#pragma unroll
        for (int i = 0; i < 4; i++) {
            const int slot = tid + 256 * i;
            const int key = slot >> 4;
            const int d0 = (slot & 15) * 4;
            const float4 vv = *(const float4*)(vb + (size_t)(j0 + key) * DHEAD + d0);
            const uint32_t cu = (uint32_t)(key >> 2);
            const uint32_t co = (uint32_t)((key & 3) * 4);
            *(float*)(smc + ATT_V + off8(d0 + 0, cu) + co) = vv.x;
            *(float*)(smc + ATT_V + off8(d0 + 1, cu) + co) = vv.y;
            *(float*)(smc + ATT_V + off8(d0 + 2, cu) + co) = vv.z;
            *(float*)(smc + ATT_V + off8(d0 + 3, cu) + co) = vv.w;
        }
        asm volatile("cp.async.wait_group 0;");
        __syncthreads();

        // ---- S = Q K^T (warp: 16 x 64) ----
        float sc[8][4];
#pragma unroll
        for (int u = 0; u < 8; u++)
#pragma unroll
            for (int r = 0; r < 4; r++) sc[u][r] = 0.f;
#pragma unroll
        for (int s = 0; s < 8; s++) {
            uint32_t a[4];
            ldsm4(a, sb + ATT_Q + (uint32_t)(qrow * 256 + (((2 * s + aub) ^ qsw) << 4)));
            uint32_t bf[8][2];
#pragma unroll
            for (int jj = 0; jj < 4; jj++) {
                uint32_t t[4];
                const int row = brow_b + 16 * jj;
                ldsm4(t, sb + ATT_K + (uint32_t)(row * 256 + (((2 * s + bub) ^ (row & 7)) << 4)));
                bf[2 * jj][0] = t[0]; bf[2 * jj][1] = t[1];
                bf[2 * jj + 1][0] = t[2]; bf[2 * jj + 1][1] = t[3];
            }
#pragma unroll
            for (int u = 0; u < 8; u++) mma_tf32(sc[u], a, bf[u]);
        }

        // ---- bias add ----
#pragma unroll
        for (int u = 0; u < 8; u++) {
            const int cc = j0 + 8 * u + 2 * tig;
            const int2 i0 = *(const int2*)(ip0 + cc);
            const int2 i1 = *(const int2*)(ip1 + cc);
            sc[u][0] += __ldg(&brow[i0.x]);
            sc[u][1] += __ldg(&brow[i0.y]);
            sc[u][2] += __ldg(&brow[i1.x]);
            sc[u][3] += __ldg(&brow[i1.y]);
        }

        // ---- online softmax (rows g, g+8; 4-lane shfl reductions) ----
#pragma unroll
        for (int a2 = 0; a2 < 2; a2++) {
            float mx = -1e30f;
#pragma unroll
            for (int u = 0; u < 8; u++)
                mx = fmaxf(mx, fmaxf(sc[u][2 * a2], sc[u][2 * a2 + 1]));
            mx = fmaxf(mx, __shfl_xor_sync(0xFFFFFFFFu, mx, 1));
            mx = fmaxf(mx, __shfl_xor_sync(0xFFFFFFFFu, mx, 2));
            const float mnew = fmaxf(mrow[a2], mx);
            const float resc = __expf(mrow[a2] - mnew);
            mrow[a2] = mnew;
            float rs = 0.f;
#pragma unroll
            for (int u = 0; u < 8; u++) {
                sc[u][2 * a2]     = __expf(sc[u][2 * a2] - mnew);
                sc[u][2 * a2 + 1] = __expf(sc[u][2 * a2 + 1] - mnew);
                rs += sc[u][2 * a2] + sc[u][2 * a2 + 1];
            }
            rs += __shfl_xor_sync(0xFFFFFFFFu, rs, 1);
            rs += __shfl_xor_sync(0xFFFFFFFFu, rs, 2);
            lrow[a2] = lrow[a2] * resc + rs;
#pragma unroll
            for (int u = 0; u < 8; u++) {
                oc[u][2 * a2]     *= resc;
                oc[u][2 * a2 + 1] *= resc;
            }
        }

        // ---- store P row-major tf32 (warp-private rows) ----
        {
            const int pr0 = 16 * w + g;
            const int pr1 = pr0 + 8;
            const uint32_t half = (uint32_t)((tig & 1) * 8);
#pragma unroll
            for (int u = 0; u < 8; u++) {
                const int lu = 2 * u + (tig >> 1);
                const uint32_t a0 = sb + ATT_P + off8(pr0, lu) + half;
                const uint32_t a1 = sb + ATT_P + off8(pr1, lu) + half;
                asm volatile("st.shared.v2.b32 [%0], {%1,%2};"
                             :: "r"(a0), "r"(f2tf32(sc[u][0])), "r"(f2tf32(sc[u][1])));
                asm volatile("st.shared.v2.b32 [%0], {%1,%2};"
                             :: "r"(a1), "r"(f2tf32(sc[u][2])), "r"(f2tf32(sc[u][3])));
            }
        }
        __syncwarp();

        // ---- O += P V  (A = P rows, B = VT[d][key]) ----
#pragma unroll
        for (int s = 0; s < 8; s++) {
            uint32_t a[4];
            ldsm4(a, sb + ATT_P + (uint32_t)(qrow * 256 + (((2 * s + aub) ^ qsw) << 4)));
            uint32_t bf[8][2];
#pragma unroll
            for (int jj = 0; jj < 4; jj++) {
                uint32_t t[4];
                const int row = brow_b + 16 * jj;
                ldsm4(t, sb + ATT_V + (uint32_t)(row * 256 + (((2 * s + bub) ^ (row & 7)) << 4)));
                bf[2 * jj][0] = t[0]; bf[2 * jj][1] = t[1];
                bf[2 * jj + 1][0] = t[2]; bf[2 * jj + 1][1] = t[3];
            }
#pragma unroll
            for (int u2 = 0; u2 < 8; u2++) mma_tf32(oc[u2], a, bf[u2]);
        }
    }

    // ---- normalize + write tf32-rounded (head-merged for out-proj) ----
    const float inv0 = 1.f / lrow[0];
    const float inv1 = 1.f / lrow[1];
    const int row0 = q0 + 16 * w + g;
#pragma unroll
    for (int u2 = 0; u2 < 8; u2++) {
        const int d = 8 * u2 + 2 * tig;
        float2 o0, o1;
        o0.x = __uint_as_float(f2tf32(oc[u2][0] * inv0));
        o0.y = __uint_as_float(f2tf32(oc[u2][1] * inv0));
        o1.x = __uint_as_float(f2tf32(oc[u2][2] * inv1));
        o1.y = __uint_as_float(f2tf32(oc[u2][3] * inv1));
        *(float2*)&g_att[((size_t)b * NSEQ + row0) * EMBD + h * DHEAD + d] = o0;
        *(float2*)&g_att[((size_t)b * NSEQ + row0 + 8) * EMBD + h * DHEAD + d] = o1;
    }
}

// ---------------------------------------------------------------------------
extern "C" void kernel_launch(void* const* d_in, const int* in_sizes, int n_in,
                              void* d_out, int out_size) {
    (void)in_sizes; (void)n_in; (void)out_size;
    const float* x      = (const float*)d_in[0];
    const float* W_qkv  = (const float*)d_in[1];
    const float* biases = (const float*)d_in[2];
    const int*   idxs   = (const int*)d_in[3];
    const float* W_out  = (const float*)d_in[4];
    const float* b_out  = (const float*)d_in[5];
    float* out = (float*)d_out;

    float* xr;  cudaGetSymbolAddress((void**)&xr, g_xr);
    float* wqr; cudaGetSymbolAddress((void**)&wqr, g_wqr);
    float* wor; cudaGetSymbolAddress((void**)&wor, g_wor);

    const int gemm_smem = 3 * STG_BYTES;   // 48 KB
    cudaFuncSetAttribute(qkv_gemm_mma, cudaFuncAttributeMaxDynamicSharedMemorySize, gemm_smem);
    cudaFuncSetAttribute(out_gemm_mma, cudaFuncAttributeMaxDynamicSharedMemorySize, gemm_smem);
    cudaFuncSetAttribute(attn_mma, cudaFuncAttributeMaxDynamicSharedMemorySize, ATT_SMEM);

    tf32_round_kernel<<<(MROWS * EMBD / 4 + 255) / 256, 256>>>((const float4*)x, (float4*)xr, MROWS * EMBD / 4);
    tf32_round_kernel<<<(3 * EMBD * EMBD / 4 + 255) / 256, 256>>>((const float4*)W_qkv, (float4*)wqr, 3 * EMBD * EMBD / 4);
    tf32_round_kernel<<<(EMBD * EMBD / 4 + 255) / 256, 256>>>((const float4*)W_out, (float4*)wor, EMBD * EMBD / 4);

    qkv_gemm_mma<<<dim3(24, 64), 256, gemm_smem>>>(xr, wqr);
    attn_mma<<<dim3(8, BATCHX * HEADS), 256, ATT_SMEM>>>(biases, idxs);
    out_gemm_mma<<<dim3(8, 64), 256, gemm_smem>>>(wor, b_out, out);
}

// round 7
// speedup vs baseline: 3.9473x; 1.1200x over previous
#include <cuda_runtime.h>
#include <cstdint>

// Problem constants
#define BATCHX 8
#define NSEQ   1024
#define EMBD   1024
#define HEADS  16
#define DHEAD  64
#define KDIM   1024
#define MROWS  (BATCHX * NSEQ)   // 8192

// Scratch (device globals: allocation-free per harness rules)
__device__ float g_q[BATCHX * HEADS * NSEQ * DHEAD];
__device__ float g_k[BATCHX * HEADS * NSEQ * DHEAD];
__device__ float g_v[BATCHX * HEADS * NSEQ * DHEAD];
__device__ float g_att[MROWS * EMBD];
__device__ float g_xr[MROWS * EMBD];          // tf32-rounded x
__device__ float g_wqr[3 * EMBD * EMBD];      // tf32-rounded W_qkv
__device__ float g_wor[EMBD * EMBD];          // tf32-rounded W_out

__device__ __forceinline__ uint32_t smem_u32(const void* p) {
    uint32_t a;
    asm("{ .reg .u64 t; cvta.to.shared.u64 t, %1; cvt.u32.u64 %0, t; }"
        : "=r"(a) : "l"(p));
    return a;
}

__device__ __forceinline__ uint32_t f2tf32(float x) {
    uint32_t y;
    asm("cvt.rna.tf32.f32 %0, %1;" : "=r"(y) : "f"(x));
    return y;
}

__device__ __forceinline__ void mma_tf32(float* c, const uint32_t* a, const uint32_t* b) {
    asm volatile(
        "mma.sync.aligned.m16n8k8.row.col.f32.tf32.tf32.f32 "
        "{%0,%1,%2,%3}, {%4,%5,%6,%7}, {%8,%9}, {%0,%1,%2,%3};"
        : "+f"(c[0]), "+f"(c[1]), "+f"(c[2]), "+f"(c[3])
        : "r"(a[0]), "r"(a[1]), "r"(a[2]), "r"(a[3]), "r"(b[0]), "r"(b[1]));
}

__device__ __forceinline__ void ldsm4(uint32_t* r, uint32_t addr) {
    asm volatile("ldmatrix.sync.aligned.m8n8.x4.shared.b16 {%0,%1,%2,%3}, [%4];"
                 : "=r"(r[0]), "=r"(r[1]), "=r"(r[2]), "=r"(r[3]) : "r"(addr));
}

__device__ __forceinline__ void cpa16(uint32_t dst, const void* src) {
    asm volatile("cp.async.cg.shared.global [%0], [%1], 16;" :: "r"(dst), "l"(src));
}

// ---------------------------------------------------------------------------
// tf32 pre-round pass
// ---------------------------------------------------------------------------
__global__ __launch_bounds__(256) void tf32_round_kernel(const float4* __restrict__ s,
                                                         float4* __restrict__ d, int n4) {
    const int i = blockIdx.x * 256 + threadIdx.x;
    if (i < n4) {
        const float4 v = s[i];
        uint4 w;
        w.x = f2tf32(v.x); w.y = f2tf32(v.y); w.z = f2tf32(v.z); w.w = f2tf32(v.w);
        d[i] = *(const float4*)&w;
    }
}

// ===========================================================================
// tf32 GEMM: cp.async 3-stage ring + ldmatrix, BK=32.
// Block 128x128, 256 thr, 8 warps (2 M x 4 N), warp tile 64x32.
// Tile rows are 128B (8 x 16B units), swizzle u ^= row&7.
// ===========================================================================
#define STG_BYTES 32768   // per stage: A 16KB + B 16KB

__device__ __forceinline__ uint32_t offG(int row, int u) {
    return (uint32_t)(row * 128 + ((u ^ (row & 7)) << 4));
}

__device__ __forceinline__ void tf32_mainloop_ca(const float* __restrict__ A,
                                                 const float* __restrict__ B,
                                                 int m0, int n0, char* sm,
                                                 float acc[4][4][4]) {
    const int tid = threadIdx.x;
    const int lane = tid & 31;
    const int wid = tid >> 5;
    const int wm = wid >> 2, wn = wid & 3;
    const uint32_t sb = smem_u32(sm);

    // loader mapping: rows lrow+32*i (i=0..3), unit lu (constant per thread)
    const int lrow = tid >> 3, lu = tid & 7;
    uint32_t oT[4];
    const float* ap[4];
    const float* bp[4];
#pragma unroll
    for (int i = 0; i < 4; i++) {
        const int row = lrow + 32 * i;
        oT[i] = offG(row, lu);
        ap[i] = A + (size_t)(m0 + row) * KDIM + lu * 4;
        bp[i] = B + (size_t)(n0 + row) * KDIM + lu * 4;
    }

#pragma unroll
    for (int i = 0; i < 4; i++)
#pragma unroll
        for (int j = 0; j < 4; j++)
#pragma unroll
            for (int r = 0; r < 4; r++) acc[i][j][r] = 0.f;

    // ldmatrix lane constants
    const int sub = lane >> 3;
    const int arow = 64 * wm + (lane & 7) + ((sub & 1) << 3);   // + 16*i
    const int aub = sub >> 1;
    const int brow = 32 * wn + (lane & 7) + ((sub >> 1) << 3);  // + 16*jj
    const int bub = sub & 1;
    const int asw = arow & 7;   // == lane&7, invariant under +16*i
    const int bsw = brow & 7;

#define G_ISSUE(st, p)                                                         \
    do {                                                                       \
        const int ko = (st) * 32;                                              \
        const uint32_t bb_ = sb + (uint32_t)(p) * STG_BYTES;                   \
        cpa16(bb_ + oT[0], ap[0] + ko);                                        \
        cpa16(bb_ + oT[1], ap[1] + ko);                                        \
        cpa16(bb_ + oT[2], ap[2] + ko);                                        \
        cpa16(bb_ + oT[3], ap[3] + ko);                                        \
        cpa16(bb_ + 16384 + oT[0], bp[0] + ko);                                \
        cpa16(bb_ + 16384 + oT[1], bp[1] + ko);                                \
        cpa16(bb_ + 16384 + oT[2], bp[2] + ko);                                \
        cpa16(bb_ + 16384 + oT[3], bp[3] + ko);                                \
    } while (0)

    G_ISSUE(0, 0);
    asm volatile("cp.async.commit_group;");
    G_ISSUE(1, 1);
    asm volatile("cp.async.commit_group;");

    const int NST = KDIM / 32;   // 32
    int p = 0;
    for (int st = 0; st < NST; st++) {
        asm volatile("cp.async.wait_group 1;");
        __syncthreads();
        const uint32_t abase = sb + (uint32_t)p * STG_BYTES;
        const uint32_t bbase = abase + 16384;
#pragma unroll
        for (int s = 0; s < 4; s++) {
            uint32_t af[4][4];
            uint32_t bf[4][2];
#pragma unroll
            for (int i = 0; i < 4; i++) {
                const int row = arow + 16 * i;
                ldsm4(af[i], abase + (uint32_t)(row * 128 + (((2 * s + aub) ^ asw) << 4)));
            }
#pragma unroll
            for (int jj = 0; jj < 2; jj++) {
                uint32_t t[4];
                const int row = brow + 16 * jj;
                ldsm4(t, bbase + (uint32_t)(row * 128 + (((2 * s + bub) ^ bsw) << 4)));
                bf[2 * jj][0] = t[0]; bf[2 * jj][1] = t[1];
                bf[2 * jj + 1][0] = t[2]; bf[2 * jj + 1][1] = t[3];
            }
#pragma unroll
            for (int i = 0; i < 4; i++)
#pragma unroll
                for (int j = 0; j < 4; j++)
                    mma_tf32(acc[i][j], af[i], bf[j]);
        }
        const int nx = st + 2;
        if (nx < NST) G_ISSUE(nx, nx % 3);
        asm volatile("cp.async.commit_group;");
        p = (p + 1) % 3;
    }
#undef G_ISSUE
}

// ---------------------------------------------------------------------------
// GEMM1: qkv = xr @ Wqkv_r^T -> scatter q (pre-scaled) / k / v, tf32-rounded
// ---------------------------------------------------------------------------
__global__ __launch_bounds__(256) void qkv_gemm_mma(const float* __restrict__ A,
                                                    const float* __restrict__ W) {
    extern __shared__ char smg[];
    const int m0 = blockIdx.y * 128;
    const int n0 = blockIdx.x * 128;
    float acc[4][4][4];
    tf32_mainloop_ca(A, W, m0, n0, smg, acc);

    const int tid = threadIdx.x;
    const int lane = tid & 31;
    const int wid = tid >> 5;
    const int wm = wid >> 2, wn = wid & 3;

    const int t = n0 >> 10;              // 0=q 1=k 2=v
    const float scale = (t == 0) ? 0.125f : 1.0f;
    float* dst = (t == 0) ? g_q : ((t == 1) ? g_k : g_v);

#pragma unroll
    for (int i = 0; i < 4; i++) {
#pragma unroll
        for (int j = 0; j < 4; j++) {
#pragma unroll
            for (int hh = 0; hh < 2; hh++) {
                const int m = m0 + 64 * wm + 16 * i + (lane >> 2) + 8 * hh;
                const int n = n0 + 32 * wn + 8 * j + 2 * (lane & 3);
                const int b = m >> 10, nn = m & 1023;
                const int e = n & 1023;
                const int h = e >> 6, d = e & 63;
                float2 o;
                o.x = __uint_as_float(f2tf32(acc[i][j][2 * hh + 0] * scale));
                o.y = __uint_as_float(f2tf32(acc[i][j][2 * hh + 1] * scale));
                *(float2*)&dst[(((size_t)b * HEADS + h) * NSEQ + nn) * DHEAD + d] = o;
            }
        }
    }
}

// ---------------------------------------------------------------------------
// GEMM2: out = g_att @ Wout_r^T + b_out
// ---------------------------------------------------------------------------
__global__ __launch_bounds__(256) void out_gemm_mma(const float* __restrict__ W,
                                                    const float* __restrict__ bias,
                                                    float* __restrict__ out) {
    extern __shared__ char smg[];
    const int m0 = blockIdx.y * 128;
    const int n0 = blockIdx.x * 128;
    float acc[4][4][4];
    tf32_mainloop_ca(g_att, W, m0, n0, smg, acc);

    const int tid = threadIdx.x;
    const int lane = tid & 31;
    const int wid = tid >> 5;
    const int wm = wid >> 2, wn = wid & 3;

#pragma unroll
    for (int i = 0; i < 4; i++) {
#pragma unroll
        for (int j = 0; j < 4; j++) {
#pragma unroll
            for (int hh = 0; hh < 2; hh++) {
                const int m = m0 + 64 * wm + 16 * i + (lane >> 2) + 8 * hh;
                const int n = n0 + 32 * wn + 8 * j + 2 * (lane & 3);
                float2 o;
                o.x = acc[i][j][2 * hh + 0] + bias[n + 0];
                o.y = acc[i][j][2 * hh + 1] + bias[n + 1];
                *(float2*)&out[(size_t)m * EMBD + n] = o;
            }
        }
    }
}

// ===========================================================================
// Tensor-core flash attention, pipelined: K double-buffered cp.async,
// V prefetched to regs during compute. Rows 256B = 16 units, swizzle u^(row&7).
//   Qs 0..32K  K0 32..48K  K1 48..64K  VT 64..80K  Ps 80..112K
// ===========================================================================
#define ATT_Q 0u
#define ATT_K0 32768u
#define ATT_V 65536u
#define ATT_P 81920u
#define ATT_SMEM 114688

__device__ __forceinline__ uint32_t off8(int row, int u) {
    return (uint32_t)(row * 256 + ((u ^ (row & 7)) << 4));
}

__global__ __launch_bounds__(256, 2) void attn_mma(const float* __restrict__ biases,
                                                   const int* __restrict__ idxs) {
    extern __shared__ char smc[];
    const uint32_t sb = smem_u32(smc);
    const int tid = threadIdx.x;
    const int lane = tid & 31;
    const int w = tid >> 5;
    const int g = lane >> 2;
    const int tig = lane & 3;

    const int q0 = blockIdx.x << 7;
    const int h = blockIdx.y & 15;
    const int b = blockIdx.y >> 4;

    const size_t bh = (size_t)(b * HEADS + h) * NSEQ * DHEAD;
    const float* qb = g_q + bh;
    const float* kb = g_k + bh;
    const float* vb = g_v + bh;
    const float* brow = biases + h * 1024;

    // ---- Q tile via cp.async (once) ----
#pragma unroll
    for (int i = 0; i < 8; i++) {
        const int slot = tid + 256 * i;
        const int row = slot >> 4, lu = slot & 15;
        cpa16(sb + ATT_Q + off8(row, lu), qb + (size_t)(q0 + row) * DHEAD + lu * 4);
    }
    // ---- K0 in same group ----
#pragma unroll
    for (int i = 0; i < 4; i++) {
        const int slot = tid + 256 * i;
        const int row = slot >> 4, lu = slot & 15;
        cpa16(sb + ATT_K0 + off8(row, lu), kb + (size_t)row * DHEAD + lu * 4);
    }
    asm volatile("cp.async.commit_group;");
    // ---- V0 LDG -> STS ----
#pragma unroll
    for (int i = 0; i < 4; i++) {
        const int slot = tid + 256 * i;
        const int key = slot >> 4;
        const int d0 = (slot & 15) * 4;
        const float4 vv = *(const float4*)(vb + (size_t)key * DHEAD + d0);
        const uint32_t cu = (uint32_t)(key >> 2);
        const uint32_t co = (uint32_t)((key & 3) * 4);
        *(float*)(smc + ATT_V + off8(d0 + 0, cu) + co) = vv.x;
        *(float*)(smc + ATT_V + off8(d0 + 1, cu) + co) = vv.y;
        *(float*)(smc + ATT_V + off8(d0 + 2, cu) + co) = vv.z;
        *(float*)(smc + ATT_V + off8(d0 + 3, cu) + co) = vv.w;
    }

    float oc[8][4];
#pragma unroll
    for (int u = 0; u < 8; u++)
#pragma unroll
        for (int r = 0; r < 4; r++) oc[u][r] = 0.f;
    float mrow[2] = {-1e30f, -1e30f};
    float lrow[2] = {0.f, 0.f};

    const int* ip0 = idxs + (size_t)(q0 + 16 * w + g) * NSEQ;
    const int* ip1 = ip0 + 8 * NSEQ;

    // ldmatrix lane constants
    const int sub = lane >> 3;
    const int qrow = 16 * w + (lane & 7) + ((sub & 1) << 3);
    const int aub = sub >> 1;
    const int brow_b = (lane & 7) + ((sub >> 1) << 3);          // + 16*jj
    const int bub = sub & 1;
    const int qsw = qrow & 7;

    for (int j0 = 0; j0 < NSEQ; j0 += 64) {
        const int p = (j0 >> 6) & 1;
        const uint32_t kcur = ATT_K0 + (uint32_t)p * 16384u;
        const uint32_t knxt = ATT_K0 + (uint32_t)(p ^ 1) * 16384u;
        const bool more = (j0 + 64 < NSEQ);
        // ---- issue next K tile ----
        if (more) {
#pragma unroll
            for (int i = 0; i < 4; i++) {
                const int slot = tid + 256 * i;
                const int row = slot >> 4, lu = slot & 15;
                cpa16(sb + knxt + off8(row, lu),
                      kb + (size_t)(j0 + 64 + row) * DHEAD + lu * 4);
            }
        }
        asm volatile("cp.async.commit_group;");
        // ---- prefetch next V into regs (in flight during compute) ----
        float4 vv2[4];
        const int jv = more ? j0 + 64 : j0;
#pragma unroll
        for (int i = 0; i < 4; i++) {
            const int slot = tid + 256 * i;
            const int key = slot >> 4;
            const int d0 = (slot & 15) * 4;
            vv2[i] = *(const float4*)(vb + (size_t)(jv + key) * DHEAD + d0);
        }
        asm volatile("cp.async.wait_group 1;");
        __syncthreads();   // K(j) ready; VT(j) visible

        // ---- S = Q K^T ----
        float sc[8][4];
#pragma unroll
        for (int u = 0; u < 8; u++)
#pragma unroll
            for (int r = 0; r < 4; r++) sc[u][r] = 0.f;
#pragma unroll
        for (int s = 0; s < 8; s++) {
            uint32_t a[4];
            ldsm4(a, sb + ATT_Q + (uint32_t)(qrow * 256 + (((2 * s + aub) ^ qsw) << 4)));
            uint32_t bf[8][2];
#pragma unroll
            for (int jj = 0; jj < 4; jj++) {
                uint32_t t[4];
                const int row = brow_b + 16 * jj;
                ldsm4(t, sb + kcur + (uint32_t)(row * 256 + (((2 * s + bub) ^ (row & 7)) << 4)));
                bf[2 * jj][0] = t[0]; bf[2 * jj][1] = t[1];
                bf[2 * jj + 1][0] = t[2]; bf[2 * jj + 1][1] = t[3];
            }
#pragma unroll
            for (int u = 0; u < 8; u++) mma_tf32(sc[u], a, bf[u]);
        }

        // ---- bias add ----
#pragma unroll
        for (int u = 0; u < 8; u++) {
            const int cc = j0 + 8 * u + 2 * tig;
            const int2 i0 = *(const int2*)(ip0 + cc);
            const int2 i1 = *(const int2*)(ip1 + cc);
            sc[u][0] += __ldg(&brow[i0.x]);
            sc[u][1] += __ldg(&brow[i0.y]);
            sc[u][2] += __ldg(&brow[i1.x]);
            sc[u][3] += __ldg(&brow[i1.y]);
        }

        // ---- online softmax ----
#pragma unroll
        for (int a2 = 0; a2 < 2; a2++) {
            float mx = -1e30f;
#pragma unroll
            for (int u = 0; u < 8; u++)
                mx = fmaxf(mx, fmaxf(sc[u][2 * a2], sc[u][2 * a2 + 1]));
            mx = fmaxf(mx, __shfl_xor_sync(0xFFFFFFFFu, mx, 1));
            mx = fmaxf(mx, __shfl_xor_sync(0xFFFFFFFFu, mx, 2));
            const float mnew = fmaxf(mrow[a2], mx);
            const float resc = __expf(mrow[a2] - mnew);
            mrow[a2] = mnew;
            float rs = 0.f;
#pragma unroll
            for (int u = 0; u < 8; u++) {
                sc[u][2 * a2]     = __expf(sc[u][2 * a2] - mnew);
                sc[u][2 * a2 + 1] = __expf(sc[u][2 * a2 + 1] - mnew);
                rs += sc[u][2 * a2] + sc[u][2 * a2 + 1];
            }
            rs += __shfl_xor_sync(0xFFFFFFFFu, rs, 1);
            rs += __shfl_xor_sync(0xFFFFFFFFu, rs, 2);
            lrow[a2] = lrow[a2] * resc + rs;
#pragma unroll
            for (int u = 0; u < 8; u++) {
                oc[u][2 * a2]     *= resc;
                oc[u][2 * a2 + 1] *= resc;
            }
        }

        // ---- store P row-major tf32 (warp-private rows) ----
        {
            const int pr0 = 16 * w + g;
            const int pr1 = pr0 + 8;
            const uint32_t half = (uint32_t)((tig & 1) * 8);
#pragma unroll
            for (int u = 0; u < 8; u++) {
                const int lu = 2 * u + (tig >> 1);
                const uint32_t a0 = sb + ATT_P + off8(pr0, lu) + half;
                const uint32_t a1 = sb + ATT_P + off8(pr1, lu) + half;
                asm volatile("st.shared.v2.b32 [%0], {%1,%2};"
                             :: "r"(a0), "r"(f2tf32(sc[u][0])), "r"(f2tf32(sc[u][1])));
                asm volatile("st.shared.v2.b32 [%0], {%1,%2};"
                             :: "r"(a1), "r"(f2tf32(sc[u][2])), "r"(f2tf32(sc[u][3])));
            }
        }
        __syncwarp();

        // ---- O += P V ----
#pragma unroll
        for (int s = 0; s < 8; s++) {
            uint32_t a[4];
            ldsm4(a, sb + ATT_P + (uint32_t)(qrow * 256 + (((2 * s + aub) ^ qsw) << 4)));
            uint32_t bf[8][2];
#pragma unroll
            for (int jj = 0; jj < 4; jj++) {
                uint32_t t[4];
                const int row = brow_b + 16 * jj;
                ldsm4(t, sb + ATT_V + (uint32_t)(row * 256 + (((2 * s + bub) ^ (row & 7)) << 4)));
                bf[2 * jj][0] = t[0]; bf[2 * jj][1] = t[1];
                bf[2 * jj + 1][0] = t[2]; bf[2 * jj + 1][1] = t[3];
            }
#pragma unroll
            for (int u2 = 0; u2 < 8; u2++) mma_tf32(oc[u2], a, bf[u2]);
        }
        __syncthreads();   // everyone done reading VT

        // ---- store prefetched V(j+1) ----
#pragma unroll
        for (int i = 0; i < 4; i++) {
            const int slot = tid + 256 * i;
            const int key = slot >> 4;
            const int d0 = (slot & 15) * 4;
            const uint32_t cu = (uint32_t)(key >> 2);
            const uint32_t co = (uint32_t)((key & 3) * 4);
            *(float*)(smc + ATT_V + off8(d0 + 0, cu) + co) = vv2[i].x;
            *(float*)(smc + ATT_V + off8(d0 + 1, cu) + co) = vv2[i].y;
            *(float*)(smc + ATT_V + off8(d0 + 2, cu) + co) = vv2[i].z;
            *(float*)(smc + ATT_V + off8(d0 + 3, cu) + co) = vv2[i].w;
        }
    }

    // ---- normalize + write tf32-rounded (head-merged for out-proj) ----
    const float inv0 = 1.f / lrow[0];
    const float inv1 = 1.f / lrow[1];
    const int row0 = q0 + 16 * w + g;
#pragma unroll
    for (int u2 = 0; u2 < 8; u2++) {
        const int d = 8 * u2 + 2 * tig;
        float2 o0, o1;
        o0.x = __uint_as_float(f2tf32(oc[u2][0] * inv0));
        o0.y = __uint_as_float(f2tf32(oc[u2][1] * inv0));
        o1.x = __uint_as_float(f2tf32(oc[u2][2] * inv1));
        o1.y = __uint_as_float(f2tf32(oc[u2][3] * inv1));
        *(float2*)&g_att[((size_t)b * NSEQ + row0) * EMBD + h * DHEAD + d] = o0;
        *(float2*)&g_att[((size_t)b * NSEQ + row0 + 8) * EMBD + h * DHEAD + d] = o1;
    }
}

// ---------------------------------------------------------------------------
extern "C" void kernel_launch(void* const* d_in, const int* in_sizes, int n_in,
                              void* d_out, int out_size) {
    (void)in_sizes; (void)n_in; (void)out_size;
    const float* x      = (const float*)d_in[0];
    const float* W_qkv  = (const float*)d_in[1];
    const float* biases = (const float*)d_in[2];
    const int*   idxs   = (const int*)d_in[3];
    const float* W_out  = (const float*)d_in[4];
    const float* b_out  = (const float*)d_in[5];
    float* out = (float*)d_out;

    float* xr;  cudaGetSymbolAddress((void**)&xr, g_xr);
    float* wqr; cudaGetSymbolAddress((void**)&wqr, g_wqr);
    float* wor; cudaGetSymbolAddress((void**)&wor, g_wor);

    const int gemm_smem = 3 * STG_BYTES;   // 96 KB
    cudaFuncSetAttribute(qkv_gemm_mma, cudaFuncAttributeMaxDynamicSharedMemorySize, gemm_smem);
    cudaFuncSetAttribute(out_gemm_mma, cudaFuncAttributeMaxDynamicSharedMemorySize, gemm_smem);
    cudaFuncSetAttribute(attn_mma, cudaFuncAttributeMaxDynamicSharedMemorySize, ATT_SMEM);

    tf32_round_kernel<<<(MROWS * EMBD / 4 + 255) / 256, 256>>>((const float4*)x, (float4*)xr, MROWS * EMBD / 4);
    tf32_round_kernel<<<(3 * EMBD * EMBD / 4 + 255) / 256, 256>>>((const float4*)W_qkv, (float4*)wqr, 3 * EMBD * EMBD / 4);
    tf32_round_kernel<<<(EMBD * EMBD / 4 + 255) / 256, 256>>>((const float4*)W_out, (float4*)wor, EMBD * EMBD / 4);

    qkv_gemm_mma<<<dim3(24, 64), 256, gemm_smem>>>(xr, wqr);
    attn_mma<<<dim3(8, BATCHX * HEADS), 256, ATT_SMEM>>>(biases, idxs);
    out_gemm_mma<<<dim3(8, 64), 256, gemm_smem>>>(wor, b_out, out);
}